// round 4
// baseline (speedup 1.0000x reference)
#include <cuda_runtime.h>
#include <cuda_fp16.h>
#include <math.h>

#define NN 100000
#define NE 3200000
#define FULLMASK 0xffffffffu

// ---------------- scratch (device globals; no runtime allocation) ----------------
__device__ int     g_src[NE];
__device__ int     g_dst[NE];
__device__ float   g_u[NE];
__device__ int2    g_se[NE];          // dst-sorted (src, u-bits)

__device__ int     g_cnt_i[NN];       // per-dst edge counts
__device__ int     g_off[NN];         // segment starts (exclusive scan)
__device__ int     g_cur[NN];         // scatter cursors; == segment end afterwards

__device__ __half2 g_y01h[NN * 32];   // layer1: half2(y0[f], y1[f]) per node
__device__ float   g_r1 [NN * 32];
__device__ float   g_h  [NN * 32];

__device__ __half2 g_z01h[NN * 16];   // layer2: half2(z0[f], z1[f]) per node
__device__ float   g_r2 [NN * 16];

__device__ int g_is64;                // edge_index layout flag

// ---------------- detect int64 vs int32 edge_index layout ----------------
__global__ void detect_kernel(const int* __restrict__ ei32) {
    if (blockIdx.x == 0 && threadIdx.x == 0) {
        int is64 = 1;
        for (int i = 0; i < 64; i++)
            if (ei32[2 * i + 1] != 0) { is64 = 0; break; }
        g_is64 = is64;
    }
}

// ---------------- zero histogram ----------------
__global__ void zero_kernel() {
    int t = blockIdx.x * blockDim.x + threadIdx.x;
    if (t < NN) g_cnt_i[t] = 0;
}

// ---------------- edge prep: decode indices, clip u, histogram dst ----------
__global__ void prep_edges(const int* __restrict__ ei32,
                           const float* __restrict__ ea) {
    int e = blockIdx.x * blockDim.x + threadIdx.x;
    if (e >= NE) return;
    int s, d;
    if (g_is64) {
        s = ei32[2 * e];
        d = ei32[2 * (NE + e)];
    } else {
        s = ei32[e];
        d = ei32[NE + e];
    }
    s = min(max(s, 0), NN - 1);
    d = min(max(d, 0), NN - 1);
    g_src[e] = s;
    g_dst[e] = d;
    g_u[e]   = fminf(fmaxf(ea[e], 0.0f), 1.0f);
    atomicAdd(&g_cnt_i[d], 1);
}

// ---------------- single-block exclusive scan of counts -> offsets/cursors ----
__global__ __launch_bounds__(1024) void scan_kernel() {
    __shared__ int sh[1024];
    const int T = 1024;
    const int C = (NN + T - 1) / T;           // 98
    int t = threadIdx.x;
    int s0 = t * C;

    int sum = 0;
    for (int i = 0; i < C; i++) {
        int idx = s0 + i;
        if (idx < NN) sum += g_cnt_i[idx];
    }
    sh[t] = sum;
    __syncthreads();
    // Hillis-Steele inclusive scan over 1024 partials
    for (int off = 1; off < T; off <<= 1) {
        int v = sh[t];
        int add = (t >= off) ? sh[t - off] : 0;
        __syncthreads();
        sh[t] = v + add;
        __syncthreads();
    }
    int run = (t == 0) ? 0 : sh[t - 1];
    for (int i = 0; i < C; i++) {
        int idx = s0 + i;
        if (idx < NN) {
            int c = g_cnt_i[idx];
            g_off[idx] = run;
            g_cur[idx] = run;
            run += c;
        }
    }
}

// ---------------- scatter edges into dst-sorted order ----------------
__global__ void scatter_kernel() {
    int e = blockIdx.x * blockDim.x + threadIdx.x;
    if (e >= NE) return;
    int d = g_dst[e];
    int pos = atomicAdd(&g_cur[d], 1);
    g_se[pos] = make_int2(g_src[e], __float_as_int(g_u[e]));
}

// ---------------- per-node GEMM: xin[N,32] @ [W0|W1|root] ----------------
template<int LAYER>
__global__ __launch_bounds__(128) void gemm_kernel(
    const float* __restrict__ xin_arg,
    const float* __restrict__ W,      // [2,32,FO]
    const float* __restrict__ root)   // [32,FO]
{
    constexpr int FO = (LAYER == 1) ? 32 : 16;
    const float* xin  = (LAYER == 1) ? xin_arg : g_h;
    __half2*     pack = (LAYER == 1) ? g_y01h : g_z01h;
    float*       rout = (LAYER == 1) ? g_r1  : g_r2;

    __shared__ __align__(16) float sW0[32 * FO];
    __shared__ __align__(16) float sW1[32 * FO];
    __shared__ __align__(16) float sR [32 * FO];

    int tid  = threadIdx.x;
    int base = blockIdx.x * 256;

    for (int i = tid; i < 32 * FO; i += 128) {
        sW0[i] = W[i];
        sW1[i] = W[32 * FO + i];
        sR [i] = root[i];
    }

    int n0 = base + 2 * tid, n1 = n0 + 1;
    float xr0[32], xr1[32];
#pragma unroll
    for (int q = 0; q < 8; q++) {
        float4 v0 = make_float4(0.f,0.f,0.f,0.f), v1 = v0;
        if (n0 < NN) v0 = *reinterpret_cast<const float4*>(&xin[(size_t)n0 * 32 + q * 4]);
        if (n1 < NN) v1 = *reinterpret_cast<const float4*>(&xin[(size_t)n1 * 32 + q * 4]);
        xr0[q*4+0]=v0.x; xr0[q*4+1]=v0.y; xr0[q*4+2]=v0.z; xr0[q*4+3]=v0.w;
        xr1[q*4+0]=v1.x; xr1[q*4+1]=v1.y; xr1[q*4+2]=v1.z; xr1[q*4+3]=v1.w;
    }
    __syncthreads();

    for (int jg = 0; jg < FO / 4; jg++) {
        float4 a0y0 = make_float4(0.f,0.f,0.f,0.f), a0y1 = a0y0;
        float4 a1y0 = a0y0, a1y1 = a0y0;
#pragma unroll
        for (int k = 0; k < 32; k++) {
            float4 w0 = *reinterpret_cast<const float4*>(&sW0[k * FO + jg * 4]);
            float4 w1 = *reinterpret_cast<const float4*>(&sW1[k * FO + jg * 4]);
            float x0 = xr0[k], x1 = xr1[k];
            a0y0.x += x0*w0.x; a0y0.y += x0*w0.y; a0y0.z += x0*w0.z; a0y0.w += x0*w0.w;
            a0y1.x += x0*w1.x; a0y1.y += x0*w1.y; a0y1.z += x0*w1.z; a0y1.w += x0*w1.w;
            a1y0.x += x1*w0.x; a1y0.y += x1*w0.y; a1y0.z += x1*w0.z; a1y0.w += x1*w0.w;
            a1y1.x += x1*w1.x; a1y1.y += x1*w1.y; a1y1.z += x1*w1.z; a1y1.w += x1*w1.w;
        }
        __half2 h0[4], h1[4];
        h0[0] = __floats2half2_rn(a0y0.x, a0y1.x);
        h0[1] = __floats2half2_rn(a0y0.y, a0y1.y);
        h0[2] = __floats2half2_rn(a0y0.z, a0y1.z);
        h0[3] = __floats2half2_rn(a0y0.w, a0y1.w);
        h1[0] = __floats2half2_rn(a1y0.x, a1y1.x);
        h1[1] = __floats2half2_rn(a1y0.y, a1y1.y);
        h1[2] = __floats2half2_rn(a1y0.z, a1y1.z);
        h1[3] = __floats2half2_rn(a1y0.w, a1y1.w);
        if (n0 < NN) *reinterpret_cast<float4*>(&pack[(size_t)n0 * FO + jg * 4]) =
            *reinterpret_cast<float4*>(h0);
        if (n1 < NN) *reinterpret_cast<float4*>(&pack[(size_t)n1 * FO + jg * 4]) =
            *reinterpret_cast<float4*>(h1);
    }

    for (int jg = 0; jg < FO / 4; jg++) {
        float4 r0 = make_float4(0.f,0.f,0.f,0.f), r1 = r0;
#pragma unroll
        for (int k = 0; k < 32; k++) {
            float4 w = *reinterpret_cast<const float4*>(&sR[k * FO + jg * 4]);
            float x0 = xr0[k], x1 = xr1[k];
            r0.x += x0*w.x; r0.y += x0*w.y; r0.z += x0*w.z; r0.w += x0*w.w;
            r1.x += x1*w.x; r1.y += x1*w.y; r1.z += x1*w.z; r1.w += x1*w.w;
        }
        if (n0 < NN) *reinterpret_cast<float4*>(&rout[(size_t)n0 * FO + jg * 4]) = r0;
        if (n1 < NN) *reinterpret_cast<float4*>(&rout[(size_t)n1 * FO + jg * 4]) = r1;
    }
}

// ---------------- layer1 segmented aggregation: warp per node, lane = feature --
// acc[f] = sum over segment of lerp(y0,y1,u)[src][f]; then fused node pass:
// h = relu(acc/max(cnt,1) + r1 + b1)
__global__ void edge_agg1(const float* __restrict__ b1) {
    int w = (blockIdx.x * blockDim.x + threadIdx.x) >> 5;
    int lane = threadIdx.x & 31;
    if (w >= NN) return;
    int start = g_off[w], end = g_cur[w];

    float acc = 0.0f;
    int e = start;
    for (; e + 4 <= end; e += 4) {
        int2 m0 = g_se[e], m1 = g_se[e+1], m2 = g_se[e+2], m3 = g_se[e+3];
        __half2 p0 = g_y01h[(size_t)m0.x * 32 + lane];
        __half2 p1 = g_y01h[(size_t)m1.x * 32 + lane];
        __half2 p2 = g_y01h[(size_t)m2.x * 32 + lane];
        __half2 p3 = g_y01h[(size_t)m3.x * 32 + lane];
        float2 f0 = __half22float2(p0); float u0 = __int_as_float(m0.y);
        float2 f1 = __half22float2(p1); float u1 = __int_as_float(m1.y);
        float2 f2 = __half22float2(p2); float u2 = __int_as_float(m2.y);
        float2 f3 = __half22float2(p3); float u3 = __int_as_float(m3.y);
        acc += f0.x + u0 * (f0.y - f0.x);
        acc += f1.x + u1 * (f1.y - f1.x);
        acc += f2.x + u2 * (f2.y - f2.x);
        acc += f3.x + u3 * (f3.y - f3.x);
    }
    for (; e < end; e++) {
        int2 m = g_se[e];
        __half2 p = g_y01h[(size_t)m.x * 32 + lane];
        float2 f = __half22float2(p);
        acc += f.x + __int_as_float(m.y) * (f.y - f.x);
    }

    float inv = 1.0f / fmaxf((float)(end - start), 1.0f);
    float h = fmaxf(acc * inv + g_r1[(size_t)w * 32 + lane] + b1[lane], 0.0f);
    g_h[(size_t)w * 32 + lane] = h;
}

// ---------------- layer2 segmented aggregation + fused log_softmax ----------
// warp per node; lanes [0..15]/[16..31] process alternating edges, f = lane&15.
__global__ void edge_agg2(const float* __restrict__ b2,
                          float* __restrict__ out) {
    int w = (blockIdx.x * blockDim.x + threadIdx.x) >> 5;
    int lane = threadIdx.x & 31;
    if (w >= NN) return;
    int start = g_off[w], end = g_cur[w];
    int f = lane & 15, half = lane >> 4;

    float acc = 0.0f;
    int e = start + half;
    for (; e + 6 < end; e += 8) {
        int2 m0 = g_se[e], m1 = g_se[e+2], m2 = g_se[e+4], m3 = g_se[e+6];
        __half2 p0 = g_z01h[(size_t)m0.x * 16 + f];
        __half2 p1 = g_z01h[(size_t)m1.x * 16 + f];
        __half2 p2 = g_z01h[(size_t)m2.x * 16 + f];
        __half2 p3 = g_z01h[(size_t)m3.x * 16 + f];
        float2 f0 = __half22float2(p0); float u0 = __int_as_float(m0.y);
        float2 f1 = __half22float2(p1); float u1 = __int_as_float(m1.y);
        float2 f2 = __half22float2(p2); float u2 = __int_as_float(m2.y);
        float2 f3 = __half22float2(p3); float u3 = __int_as_float(m3.y);
        acc += f0.x + u0 * (f0.y - f0.x);
        acc += f1.x + u1 * (f1.y - f1.x);
        acc += f2.x + u2 * (f2.y - f2.x);
        acc += f3.x + u3 * (f3.y - f3.x);
    }
    for (; e < end; e += 2) {
        int2 m = g_se[e];
        __half2 p = g_z01h[(size_t)m.x * 16 + f];
        float2 ff = __half22float2(p);
        acc += ff.x + __int_as_float(m.y) * (ff.y - ff.x);
    }
    // combine the two half-warps
    acc += __shfl_xor_sync(FULLMASK, acc, 16);

    float inv = 1.0f / fmaxf((float)(end - start), 1.0f);
    float v = acc * inv + g_r2[(size_t)w * 16 + f] + b2[f];

    // log_softmax over the 16 features (both half-warps hold identical v sets)
    float m = v;
#pragma unroll
    for (int off = 8; off >= 1; off >>= 1)
        m = fmaxf(m, __shfl_xor_sync(FULLMASK, m, off));
    float s = expf(v - m);
#pragma unroll
    for (int off = 8; off >= 1; off >>= 1)
        s += __shfl_xor_sync(FULLMASK, s, off);
    float lo = logf(s);
    if (lane < 16)
        out[(size_t)w * 16 + f] = v - m - lo;
}

// ---------------- launch ----------------
extern "C" void kernel_launch(void* const* d_in, const int* in_sizes, int n_in,
                              void* d_out, int out_size) {
    const float* x   = (const float*)d_in[0];
    const int*   ei  = (const int*)d_in[1];
    const float* ea  = (const float*)d_in[2];
    const float* W1  = (const float*)d_in[3];
    const float* r1w = (const float*)d_in[4];
    const float* b1  = (const float*)d_in[5];
    const float* W2  = (const float*)d_in[6];
    const float* r2w = (const float*)d_in[7];
    const float* b2  = (const float*)d_in[8];
    float* out = (float*)d_out;

    detect_kernel<<<1, 32>>>(ei);
    zero_kernel<<<(NN + 255) / 256, 256>>>();
    prep_edges<<<(NE + 255) / 256, 256>>>(ei, ea);
    scan_kernel<<<1, 1024>>>();
    scatter_kernel<<<(NE + 255) / 256, 256>>>();

    gemm_kernel<1><<<(NN + 255) / 256, 128>>>(x, W1, r1w);
    edge_agg1<<<(NN * 32 + 255) / 256, 256>>>(b1);

    gemm_kernel<2><<<(NN + 255) / 256, 128>>>(nullptr, W2, r2w);
    edge_agg2<<<(NN * 32 + 255) / 256, 256>>>(b2, out);
}

// round 5
// speedup vs baseline: 1.6225x; 1.6225x over previous
#include <cuda_runtime.h>
#include <cuda_fp16.h>
#include <math.h>

#define NN 100000
#define NE 3200000
#define FULLMASK 0xffffffffu
#define SCAN_B   1024
#define SCAN_NB  ((NN + SCAN_B - 1) / SCAN_B)   // 98

// ---------------- scratch (device globals; no runtime allocation) ----------------
__device__ int2    g_se[NE];          // dst-sorted (src, u-bits)

__device__ int     g_cnt_i[NN];       // per-dst edge counts
__device__ int     g_off[NN];         // segment starts (exclusive scan)
__device__ int     g_cur[NN];         // scatter cursors; == segment end afterwards
__device__ int     g_bsum[SCAN_NB];   // per-block count sums
__device__ int     g_boff[SCAN_NB];   // per-block exclusive offsets

__device__ __half2 g_y01h[NN * 32];   // layer1: half2(y0[f], y1[f]) per node
__device__ float   g_r1 [NN * 32];
__device__ float   g_h  [NN * 32];

__device__ __half2 g_z01h[NN * 16];   // layer2: half2(z0[f], z1[f]) per node
__device__ float   g_r2 [NN * 16];

__device__ int g_is64;                // edge_index layout flag

// ---------------- detect int64 vs int32 edge_index layout ----------------
__global__ void detect_kernel(const int* __restrict__ ei32) {
    if (blockIdx.x == 0 && threadIdx.x == 0) {
        int is64 = 1;
        for (int i = 0; i < 64; i++)
            if (ei32[2 * i + 1] != 0) { is64 = 0; break; }
        g_is64 = is64;
    }
}

// ---------------- zero histogram ----------------
__global__ void zero_kernel() {
    int t = blockIdx.x * blockDim.x + threadIdx.x;
    if (t < NN) g_cnt_i[t] = 0;
}

// ---------------- histogram of dst ----------------
__global__ void prep_hist(const int* __restrict__ ei32) {
    int e = blockIdx.x * blockDim.x + threadIdx.x;
    if (e >= NE) return;
    int d = g_is64 ? ei32[2 * (NE + e)] : ei32[NE + e];
    d = min(max(d, 0), NN - 1);
    atomicAdd(&g_cnt_i[d], 1);
}

// ---------------- parallel scan, phase 1: per-block sums ----------------
__global__ __launch_bounds__(256) void scan_phase1() {
    __shared__ int sh[256];
    int b = blockIdx.x, t = threadIdx.x;
    int base = b * SCAN_B;
    int s = 0;
    for (int i = t; i < SCAN_B; i += 256) {
        int idx = base + i;
        if (idx < NN) s += g_cnt_i[idx];
    }
    sh[t] = s;
    __syncthreads();
    for (int o = 128; o > 0; o >>= 1) {
        if (t < o) sh[t] += sh[t + o];
        __syncthreads();
    }
    if (t == 0) g_bsum[b] = sh[0];
}

// ---------------- phase 2: scan the 98 block sums (1 block) ----------------
__global__ __launch_bounds__(128) void scan_phase2() {
    __shared__ int sh[128];
    int t = threadIdx.x;
    sh[t] = (t < SCAN_NB) ? g_bsum[t] : 0;
    __syncthreads();
    for (int o = 1; o < 128; o <<= 1) {
        int add = (t >= o) ? sh[t - o] : 0;
        __syncthreads();
        sh[t] += add;
        __syncthreads();
    }
    if (t < SCAN_NB) g_boff[t] = (t == 0) ? 0 : sh[t - 1];
}

// ---------------- phase 3: local scan + block offset -> g_off / g_cur --------
__global__ __launch_bounds__(SCAN_B) void scan_phase3() {
    __shared__ int sh[SCAN_B];
    int b = blockIdx.x, t = threadIdx.x;
    int idx = b * SCAN_B + t;
    int c = (idx < NN) ? g_cnt_i[idx] : 0;
    sh[t] = c;
    __syncthreads();
    for (int o = 1; o < SCAN_B; o <<= 1) {
        int add = (t >= o) ? sh[t - o] : 0;
        __syncthreads();
        sh[t] += add;
        __syncthreads();
    }
    if (idx < NN) {
        int off = g_boff[b] + sh[t] - c;   // exclusive
        g_off[idx] = off;
        g_cur[idx] = off;
    }
}

// ---------------- scatter edges into dst-sorted order (decodes from inputs) ---
__global__ void scatter_kernel(const int* __restrict__ ei32,
                               const float* __restrict__ ea) {
    int e = blockIdx.x * blockDim.x + threadIdx.x;
    if (e >= NE) return;
    int s, d;
    if (g_is64) {
        s = ei32[2 * e];
        d = ei32[2 * (NE + e)];
    } else {
        s = ei32[e];
        d = ei32[NE + e];
    }
    s = min(max(s, 0), NN - 1);
    d = min(max(d, 0), NN - 1);
    float u = fminf(fmaxf(ea[e], 0.0f), 1.0f);
    int pos = atomicAdd(&g_cur[d], 1);
    g_se[pos] = make_int2(s, __float_as_int(u));
}

// ---------------- per-node GEMM: xin[N,32] @ [W0|W1|root] ----------------
template<int LAYER>
__global__ __launch_bounds__(128) void gemm_kernel(
    const float* __restrict__ xin_arg,
    const float* __restrict__ W,      // [2,32,FO]
    const float* __restrict__ root)   // [32,FO]
{
    constexpr int FO = (LAYER == 1) ? 32 : 16;
    const float* xin  = (LAYER == 1) ? xin_arg : g_h;
    __half2*     pack = (LAYER == 1) ? g_y01h : g_z01h;
    float*       rout = (LAYER == 1) ? g_r1  : g_r2;

    __shared__ __align__(16) float sW0[32 * FO];
    __shared__ __align__(16) float sW1[32 * FO];
    __shared__ __align__(16) float sR [32 * FO];

    int tid  = threadIdx.x;
    int base = blockIdx.x * 256;

    for (int i = tid; i < 32 * FO; i += 128) {
        sW0[i] = W[i];
        sW1[i] = W[32 * FO + i];
        sR [i] = root[i];
    }

    int n0 = base + 2 * tid, n1 = n0 + 1;
    float xr0[32], xr1[32];
#pragma unroll
    for (int q = 0; q < 8; q++) {
        float4 v0 = make_float4(0.f,0.f,0.f,0.f), v1 = v0;
        if (n0 < NN) v0 = *reinterpret_cast<const float4*>(&xin[(size_t)n0 * 32 + q * 4]);
        if (n1 < NN) v1 = *reinterpret_cast<const float4*>(&xin[(size_t)n1 * 32 + q * 4]);
        xr0[q*4+0]=v0.x; xr0[q*4+1]=v0.y; xr0[q*4+2]=v0.z; xr0[q*4+3]=v0.w;
        xr1[q*4+0]=v1.x; xr1[q*4+1]=v1.y; xr1[q*4+2]=v1.z; xr1[q*4+3]=v1.w;
    }
    __syncthreads();

    for (int jg = 0; jg < FO / 4; jg++) {
        float4 a0y0 = make_float4(0.f,0.f,0.f,0.f), a0y1 = a0y0;
        float4 a1y0 = a0y0, a1y1 = a0y0;
#pragma unroll
        for (int k = 0; k < 32; k++) {
            float4 w0 = *reinterpret_cast<const float4*>(&sW0[k * FO + jg * 4]);
            float4 w1 = *reinterpret_cast<const float4*>(&sW1[k * FO + jg * 4]);
            float x0 = xr0[k], x1 = xr1[k];
            a0y0.x += x0*w0.x; a0y0.y += x0*w0.y; a0y0.z += x0*w0.z; a0y0.w += x0*w0.w;
            a0y1.x += x0*w1.x; a0y1.y += x0*w1.y; a0y1.z += x0*w1.z; a0y1.w += x0*w1.w;
            a1y0.x += x1*w0.x; a1y0.y += x1*w0.y; a1y0.z += x1*w0.z; a1y0.w += x1*w0.w;
            a1y1.x += x1*w1.x; a1y1.y += x1*w1.y; a1y1.z += x1*w1.z; a1y1.w += x1*w1.w;
        }
        __half2 h0[4], h1[4];
        h0[0] = __floats2half2_rn(a0y0.x, a0y1.x);
        h0[1] = __floats2half2_rn(a0y0.y, a0y1.y);
        h0[2] = __floats2half2_rn(a0y0.z, a0y1.z);
        h0[3] = __floats2half2_rn(a0y0.w, a0y1.w);
        h1[0] = __floats2half2_rn(a1y0.x, a1y1.x);
        h1[1] = __floats2half2_rn(a1y0.y, a1y1.y);
        h1[2] = __floats2half2_rn(a1y0.z, a1y1.z);
        h1[3] = __floats2half2_rn(a1y0.w, a1y1.w);
        if (n0 < NN) *reinterpret_cast<float4*>(&pack[(size_t)n0 * FO + jg * 4]) =
            *reinterpret_cast<float4*>(h0);
        if (n1 < NN) *reinterpret_cast<float4*>(&pack[(size_t)n1 * FO + jg * 4]) =
            *reinterpret_cast<float4*>(h1);
    }

    for (int jg = 0; jg < FO / 4; jg++) {
        float4 r0 = make_float4(0.f,0.f,0.f,0.f), r1 = r0;
#pragma unroll
        for (int k = 0; k < 32; k++) {
            float4 w = *reinterpret_cast<const float4*>(&sR[k * FO + jg * 4]);
            float x0 = xr0[k], x1 = xr1[k];
            r0.x += x0*w.x; r0.y += x0*w.y; r0.z += x0*w.z; r0.w += x0*w.w;
            r1.x += x1*w.x; r1.y += x1*w.y; r1.z += x1*w.z; r1.w += x1*w.w;
        }
        if (n0 < NN) *reinterpret_cast<float4*>(&rout[(size_t)n0 * FO + jg * 4]) = r0;
        if (n1 < NN) *reinterpret_cast<float4*>(&rout[(size_t)n1 * FO + jg * 4]) = r1;
    }
}

// ---------------- layer1 segmented aggregation: warp per node, lane = feature --
__global__ void edge_agg1(const float* __restrict__ b1) {
    int w = (blockIdx.x * blockDim.x + threadIdx.x) >> 5;
    int lane = threadIdx.x & 31;
    if (w >= NN) return;
    int start = g_off[w], end = g_cur[w];

    float acc = 0.0f;
    int e = start;
    for (; e + 4 <= end; e += 4) {
        int2 m0 = g_se[e], m1 = g_se[e+1], m2 = g_se[e+2], m3 = g_se[e+3];
        __half2 p0 = g_y01h[(size_t)m0.x * 32 + lane];
        __half2 p1 = g_y01h[(size_t)m1.x * 32 + lane];
        __half2 p2 = g_y01h[(size_t)m2.x * 32 + lane];
        __half2 p3 = g_y01h[(size_t)m3.x * 32 + lane];
        float2 f0 = __half22float2(p0); float u0 = __int_as_float(m0.y);
        float2 f1 = __half22float2(p1); float u1 = __int_as_float(m1.y);
        float2 f2 = __half22float2(p2); float u2 = __int_as_float(m2.y);
        float2 f3 = __half22float2(p3); float u3 = __int_as_float(m3.y);
        acc += f0.x + u0 * (f0.y - f0.x);
        acc += f1.x + u1 * (f1.y - f1.x);
        acc += f2.x + u2 * (f2.y - f2.x);
        acc += f3.x + u3 * (f3.y - f3.x);
    }
    for (; e < end; e++) {
        int2 m = g_se[e];
        __half2 p = g_y01h[(size_t)m.x * 32 + lane];
        float2 f = __half22float2(p);
        acc += f.x + __int_as_float(m.y) * (f.y - f.x);
    }

    float inv = 1.0f / fmaxf((float)(end - start), 1.0f);
    float h = fmaxf(acc * inv + g_r1[(size_t)w * 32 + lane] + b1[lane], 0.0f);
    g_h[(size_t)w * 32 + lane] = h;
}

// ---------------- layer2 segmented aggregation + fused log_softmax ----------
__global__ void edge_agg2(const float* __restrict__ b2,
                          float* __restrict__ out) {
    int w = (blockIdx.x * blockDim.x + threadIdx.x) >> 5;
    int lane = threadIdx.x & 31;
    if (w >= NN) return;
    int start = g_off[w], end = g_cur[w];
    int f = lane & 15, half = lane >> 4;

    float acc = 0.0f;
    int e = start + half;
    for (; e + 6 < end; e += 8) {
        int2 m0 = g_se[e], m1 = g_se[e+2], m2 = g_se[e+4], m3 = g_se[e+6];
        __half2 p0 = g_z01h[(size_t)m0.x * 16 + f];
        __half2 p1 = g_z01h[(size_t)m1.x * 16 + f];
        __half2 p2 = g_z01h[(size_t)m2.x * 16 + f];
        __half2 p3 = g_z01h[(size_t)m3.x * 16 + f];
        float2 f0 = __half22float2(p0); float u0 = __int_as_float(m0.y);
        float2 f1 = __half22float2(p1); float u1 = __int_as_float(m1.y);
        float2 f2 = __half22float2(p2); float u2 = __int_as_float(m2.y);
        float2 f3 = __half22float2(p3); float u3 = __int_as_float(m3.y);
        acc += f0.x + u0 * (f0.y - f0.x);
        acc += f1.x + u1 * (f1.y - f1.x);
        acc += f2.x + u2 * (f2.y - f2.x);
        acc += f3.x + u3 * (f3.y - f3.x);
    }
    for (; e < end; e += 2) {
        int2 m = g_se[e];
        __half2 p = g_z01h[(size_t)m.x * 16 + f];
        float2 ff = __half22float2(p);
        acc += ff.x + __int_as_float(m.y) * (ff.y - ff.x);
    }
    acc += __shfl_xor_sync(FULLMASK, acc, 16);

    float inv = 1.0f / fmaxf((float)(end - start), 1.0f);
    float v = acc * inv + g_r2[(size_t)w * 16 + f] + b2[f];

    float m = v;
#pragma unroll
    for (int off = 8; off >= 1; off >>= 1)
        m = fmaxf(m, __shfl_xor_sync(FULLMASK, m, off));
    float s = expf(v - m);
#pragma unroll
    for (int off = 8; off >= 1; off >>= 1)
        s += __shfl_xor_sync(FULLMASK, s, off);
    float lo = logf(s);
    if (lane < 16)
        out[(size_t)w * 16 + f] = v - m - lo;
}

// ---------------- launch ----------------
extern "C" void kernel_launch(void* const* d_in, const int* in_sizes, int n_in,
                              void* d_out, int out_size) {
    const float* x   = (const float*)d_in[0];
    const int*   ei  = (const int*)d_in[1];
    const float* ea  = (const float*)d_in[2];
    const float* W1  = (const float*)d_in[3];
    const float* r1w = (const float*)d_in[4];
    const float* b1  = (const float*)d_in[5];
    const float* W2  = (const float*)d_in[6];
    const float* r2w = (const float*)d_in[7];
    const float* b2  = (const float*)d_in[8];
    float* out = (float*)d_out;

    detect_kernel<<<1, 32>>>(ei);
    zero_kernel<<<(NN + 255) / 256, 256>>>();
    prep_hist<<<(NE + 255) / 256, 256>>>(ei);
    scan_phase1<<<SCAN_NB, 256>>>();
    scan_phase2<<<1, 128>>>();
    scan_phase3<<<SCAN_NB, SCAN_B>>>();
    scatter_kernel<<<(NE + 255) / 256, 256>>>(ei, ea);

    gemm_kernel<1><<<(NN + 255) / 256, 128>>>(x, W1, r1w);
    edge_agg1<<<(NN * 32 + 255) / 256, 256>>>(b1);

    gemm_kernel<2><<<(NN + 255) / 256, 128>>>(nullptr, W2, r2w);
    edge_agg2<<<(NN * 32 + 255) / 256, 256>>>(b2, out);
}

// round 6
// speedup vs baseline: 1.6900x; 1.0416x over previous
#include <cuda_runtime.h>
#include <cuda_fp16.h>
#include <math.h>

#define NN 100000
#define NE 3200000
#define FULLMASK 0xffffffffu
#define SCAN_B   1024
#define SCAN_NB  ((NN + SCAN_B - 1) / SCAN_B)   // 98
#define GB1      ((NN + 255) / 256)             // 391 gemm blocks (layer1)
#define HB       2048                            // histogram blocks in fused kernel

// ---------------- scratch (device globals; no runtime allocation) ----------------
__device__ int2    g_se[NE];          // dst-sorted (src, u-bits)

__device__ int     g_cnt_i[NN];       // per-dst edge counts
__device__ int     g_off[NN];         // segment starts (exclusive scan)
__device__ int     g_cur[NN];         // scatter cursors; == segment end afterwards
__device__ int     g_bsum[SCAN_NB];   // per-block count sums
__device__ int     g_boff[SCAN_NB];   // per-block exclusive offsets

__device__ __half2 g_y01h[NN * 32];   // layer1: half2(y0[f], y1[f]) per node
__device__ float   g_r1 [NN * 32];
__device__ float   g_h  [NN * 32];

__device__ __half2 g_z01h[NN * 16];   // layer2: half2(z0[f], z1[f]) per node
__device__ float   g_r2 [NN * 16];

__device__ int g_is64;                // edge_index layout flag

// ---------------- init: detect int64-vs-int32 layout + zero histogram ----------
__global__ void init_kernel(const int* __restrict__ ei32) {
    int t = blockIdx.x * blockDim.x + threadIdx.x;
    if (t == 0) {
        int is64 = 1;
        for (int i = 0; i < 64; i++)
            if (ei32[2 * i + 1] != 0) { is64 = 0; break; }
        g_is64 = is64;
    }
    if (t < NN) g_cnt_i[t] = 0;
}

// ---------------- shared GEMM body: one node per thread, 256 thr/block --------
// out: pack[n][f] = half2(y0[f], y1[f]);  rout[n][f] = x @ root.
template<int FO>
__device__ __forceinline__ void gemm_body(
    const float* __restrict__ xin,
    const float* __restrict__ W,      // [2,32,FO]
    const float* __restrict__ root,   // [32,FO]
    __half2* __restrict__ pack,
    float*   __restrict__ rout,
    int base)
{
    __shared__ __align__(16) float sW0[32 * FO];
    __shared__ __align__(16) float sW1[32 * FO];
    __shared__ __align__(16) float sR [32 * FO];
    int tid = threadIdx.x;

    for (int i = tid; i < 32 * FO; i += 256) {
        sW0[i] = W[i];
        sW1[i] = W[32 * FO + i];
        sR [i] = root[i];
    }

    int n = base + tid;
    float xr[32];
#pragma unroll
    for (int q = 0; q < 8; q++) {
        float4 v = make_float4(0.f, 0.f, 0.f, 0.f);
        if (n < NN) v = *reinterpret_cast<const float4*>(&xin[(size_t)n * 32 + q * 4]);
        xr[q*4+0] = v.x; xr[q*4+1] = v.y; xr[q*4+2] = v.z; xr[q*4+3] = v.w;
    }
    __syncthreads();

#pragma unroll
    for (int jg = 0; jg < FO / 4; jg++) {
        float4 ay0 = make_float4(0.f,0.f,0.f,0.f);
        float4 ay1 = ay0, ar = ay0;
#pragma unroll
        for (int k = 0; k < 32; k++) {
            float4 w0 = *reinterpret_cast<const float4*>(&sW0[k * FO + jg * 4]);
            float4 w1 = *reinterpret_cast<const float4*>(&sW1[k * FO + jg * 4]);
            float4 wr = *reinterpret_cast<const float4*>(&sR [k * FO + jg * 4]);
            float xk = xr[k];
            ay0.x += xk*w0.x; ay0.y += xk*w0.y; ay0.z += xk*w0.z; ay0.w += xk*w0.w;
            ay1.x += xk*w1.x; ay1.y += xk*w1.y; ay1.z += xk*w1.z; ay1.w += xk*w1.w;
            ar.x  += xk*wr.x; ar.y  += xk*wr.y; ar.z  += xk*wr.z; ar.w  += xk*wr.w;
        }
        if (n < NN) {
            __half2 h[4];
            h[0] = __floats2half2_rn(ay0.x, ay1.x);
            h[1] = __floats2half2_rn(ay0.y, ay1.y);
            h[2] = __floats2half2_rn(ay0.z, ay1.z);
            h[3] = __floats2half2_rn(ay0.w, ay1.w);
            *reinterpret_cast<float4*>(&pack[(size_t)n * FO + jg * 4]) =
                *reinterpret_cast<float4*>(h);
            *reinterpret_cast<float4*>(&rout[(size_t)n * FO + jg * 4]) =
                make_float4(ar.x, ar.y, ar.z, ar.w);
        }
    }
}

// ---------------- fused: layer1 GEMM (blocks < GB1) + dst histogram ----------
__global__ __launch_bounds__(256) void gemm1_hist(
    const float* __restrict__ x,
    const float* __restrict__ W,
    const float* __restrict__ root,
    const int*   __restrict__ ei32)
{
    if (blockIdx.x < GB1) {
        gemm_body<32>(x, W, root, g_y01h, g_r1, blockIdx.x * 256);
        return;
    }
    int b = blockIdx.x - GB1;
    int is64 = g_is64;
    for (int e = b * 256 + threadIdx.x; e < NE; e += HB * 256) {
        int d = is64 ? ei32[2 * (NE + e)] : ei32[NE + e];
        d = min(max(d, 0), NN - 1);
        atomicAdd(&g_cnt_i[d], 1);
    }
}

// ---------------- layer2 GEMM ----------------
__global__ __launch_bounds__(256) void gemm2_kernel(
    const float* __restrict__ W,
    const float* __restrict__ root)
{
    gemm_body<16>(g_h, W, root, g_z01h, g_r2, blockIdx.x * 256);
}

// ---------------- parallel scan, phase 1: per-block sums ----------------
__global__ __launch_bounds__(256) void scan_phase1() {
    __shared__ int sh[256];
    int b = blockIdx.x, t = threadIdx.x;
    int base = b * SCAN_B;
    int s = 0;
    for (int i = t; i < SCAN_B; i += 256) {
        int idx = base + i;
        if (idx < NN) s += g_cnt_i[idx];
    }
    sh[t] = s;
    __syncthreads();
    for (int o = 128; o > 0; o >>= 1) {
        if (t < o) sh[t] += sh[t + o];
        __syncthreads();
    }
    if (t == 0) g_bsum[b] = sh[0];
}

// ---------------- phase 2: scan the 98 block sums (1 block) ----------------
__global__ __launch_bounds__(128) void scan_phase2() {
    __shared__ int sh[128];
    int t = threadIdx.x;
    sh[t] = (t < SCAN_NB) ? g_bsum[t] : 0;
    __syncthreads();
    for (int o = 1; o < 128; o <<= 1) {
        int add = (t >= o) ? sh[t - o] : 0;
        __syncthreads();
        sh[t] += add;
        __syncthreads();
    }
    if (t < SCAN_NB) g_boff[t] = (t == 0) ? 0 : sh[t - 1];
}

// ---------------- phase 3: local scan + block offset -> g_off / g_cur --------
__global__ __launch_bounds__(SCAN_B) void scan_phase3() {
    __shared__ int sh[SCAN_B];
    int b = blockIdx.x, t = threadIdx.x;
    int idx = b * SCAN_B + t;
    int c = (idx < NN) ? g_cnt_i[idx] : 0;
    sh[t] = c;
    __syncthreads();
    for (int o = 1; o < SCAN_B; o <<= 1) {
        int add = (t >= o) ? sh[t - o] : 0;
        __syncthreads();
        sh[t] += add;
        __syncthreads();
    }
    if (idx < NN) {
        int off = g_boff[b] + sh[t] - c;   // exclusive
        g_off[idx] = off;
        g_cur[idx] = off;
    }
}

// ---------------- scatter edges into dst-sorted order ----------------
__global__ void scatter_kernel(const int* __restrict__ ei32,
                               const float* __restrict__ ea) {
    int e = blockIdx.x * blockDim.x + threadIdx.x;
    if (e >= NE) return;
    int s, d;
    if (g_is64) {
        s = ei32[2 * e];
        d = ei32[2 * (NE + e)];
    } else {
        s = ei32[e];
        d = ei32[NE + e];
    }
    s = min(max(s, 0), NN - 1);
    d = min(max(d, 0), NN - 1);
    float u = fminf(fmaxf(ea[e], 0.0f), 1.0f);
    int pos = atomicAdd(&g_cur[d], 1);
    g_se[pos] = make_int2(s, __float_as_int(u));
}

// ---------------- layer1 segmented aggregation: warp per node, lane = feature --
__global__ void edge_agg1(const float* __restrict__ b1) {
    int w = (blockIdx.x * blockDim.x + threadIdx.x) >> 5;
    int lane = threadIdx.x & 31;
    if (w >= NN) return;
    int start = g_off[w], end = g_cur[w];

    float acc_a = 0.0f, acc_b = 0.0f;
    int e = start;
    for (; e + 8 <= end; e += 8) {
        int2 m0 = g_se[e],   m1 = g_se[e+1], m2 = g_se[e+2], m3 = g_se[e+3];
        int2 m4 = g_se[e+4], m5 = g_se[e+5], m6 = g_se[e+6], m7 = g_se[e+7];
        __half2 p0 = g_y01h[(size_t)m0.x * 32 + lane];
        __half2 p1 = g_y01h[(size_t)m1.x * 32 + lane];
        __half2 p2 = g_y01h[(size_t)m2.x * 32 + lane];
        __half2 p3 = g_y01h[(size_t)m3.x * 32 + lane];
        __half2 p4 = g_y01h[(size_t)m4.x * 32 + lane];
        __half2 p5 = g_y01h[(size_t)m5.x * 32 + lane];
        __half2 p6 = g_y01h[(size_t)m6.x * 32 + lane];
        __half2 p7 = g_y01h[(size_t)m7.x * 32 + lane];
        float2 f0 = __half22float2(p0); float u0 = __int_as_float(m0.y);
        float2 f1 = __half22float2(p1); float u1 = __int_as_float(m1.y);
        float2 f2 = __half22float2(p2); float u2 = __int_as_float(m2.y);
        float2 f3 = __half22float2(p3); float u3 = __int_as_float(m3.y);
        float2 f4 = __half22float2(p4); float u4 = __int_as_float(m4.y);
        float2 f5 = __half22float2(p5); float u5 = __int_as_float(m5.y);
        float2 f6 = __half22float2(p6); float u6 = __int_as_float(m6.y);
        float2 f7 = __half22float2(p7); float u7 = __int_as_float(m7.y);
        acc_a += f0.x + u0 * (f0.y - f0.x);
        acc_a += f1.x + u1 * (f1.y - f1.x);
        acc_a += f2.x + u2 * (f2.y - f2.x);
        acc_a += f3.x + u3 * (f3.y - f3.x);
        acc_b += f4.x + u4 * (f4.y - f4.x);
        acc_b += f5.x + u5 * (f5.y - f5.x);
        acc_b += f6.x + u6 * (f6.y - f6.x);
        acc_b += f7.x + u7 * (f7.y - f7.x);
    }
    for (; e < end; e++) {
        int2 m = g_se[e];
        __half2 p = g_y01h[(size_t)m.x * 32 + lane];
        float2 f = __half22float2(p);
        acc_a += f.x + __int_as_float(m.y) * (f.y - f.x);
    }
    float acc = acc_a + acc_b;

    float inv = 1.0f / fmaxf((float)(end - start), 1.0f);
    float h = fmaxf(acc * inv + g_r1[(size_t)w * 32 + lane] + b1[lane], 0.0f);
    g_h[(size_t)w * 32 + lane] = h;
}

// ---------------- layer2 segmented aggregation + fused log_softmax ----------
__global__ void edge_agg2(const float* __restrict__ b2,
                          float* __restrict__ out) {
    int w = (blockIdx.x * blockDim.x + threadIdx.x) >> 5;
    int lane = threadIdx.x & 31;
    if (w >= NN) return;
    int start = g_off[w], end = g_cur[w];
    int f = lane & 15, half = lane >> 4;

    float acc = 0.0f;
    int e = start + half;
    for (; e + 6 < end; e += 8) {
        int2 m0 = g_se[e], m1 = g_se[e+2], m2 = g_se[e+4], m3 = g_se[e+6];
        __half2 p0 = g_z01h[(size_t)m0.x * 16 + f];
        __half2 p1 = g_z01h[(size_t)m1.x * 16 + f];
        __half2 p2 = g_z01h[(size_t)m2.x * 16 + f];
        __half2 p3 = g_z01h[(size_t)m3.x * 16 + f];
        float2 f0 = __half22float2(p0); float u0 = __int_as_float(m0.y);
        float2 f1 = __half22float2(p1); float u1 = __int_as_float(m1.y);
        float2 f2 = __half22float2(p2); float u2 = __int_as_float(m2.y);
        float2 f3 = __half22float2(p3); float u3 = __int_as_float(m3.y);
        acc += f0.x + u0 * (f0.y - f0.x);
        acc += f1.x + u1 * (f1.y - f1.x);
        acc += f2.x + u2 * (f2.y - f2.x);
        acc += f3.x + u3 * (f3.y - f3.x);
    }
    for (; e < end; e += 2) {
        int2 m = g_se[e];
        __half2 p = g_z01h[(size_t)m.x * 16 + f];
        float2 ff = __half22float2(p);
        acc += ff.x + __int_as_float(m.y) * (ff.y - ff.x);
    }
    acc += __shfl_xor_sync(FULLMASK, acc, 16);

    float inv = 1.0f / fmaxf((float)(end - start), 1.0f);
    float v = acc * inv + g_r2[(size_t)w * 16 + f] + b2[f];

    float m = v;
#pragma unroll
    for (int off = 8; off >= 1; off >>= 1)
        m = fmaxf(m, __shfl_xor_sync(FULLMASK, m, off));
    float s = expf(v - m);
#pragma unroll
    for (int off = 8; off >= 1; off >>= 1)
        s += __shfl_xor_sync(FULLMASK, s, off);
    float lo = logf(s);
    if (lane < 16)
        out[(size_t)w * 16 + f] = v - m - lo;
}

// ---------------- launch ----------------
extern "C" void kernel_launch(void* const* d_in, const int* in_sizes, int n_in,
                              void* d_out, int out_size) {
    const float* x   = (const float*)d_in[0];
    const int*   ei  = (const int*)d_in[1];
    const float* ea  = (const float*)d_in[2];
    const float* W1  = (const float*)d_in[3];
    const float* r1w = (const float*)d_in[4];
    const float* b1  = (const float*)d_in[5];
    const float* W2  = (const float*)d_in[6];
    const float* r2w = (const float*)d_in[7];
    const float* b2  = (const float*)d_in[8];
    float* out = (float*)d_out;

    init_kernel<<<(NN + 255) / 256, 256>>>(ei);
    gemm1_hist<<<GB1 + HB, 256>>>(x, W1, r1w, ei);
    scan_phase1<<<SCAN_NB, 256>>>();
    scan_phase2<<<1, 128>>>();
    scan_phase3<<<SCAN_NB, SCAN_B>>>();
    scatter_kernel<<<(NE + 255) / 256, 256>>>(ei, ea);

    edge_agg1<<<(NN * 32 + 255) / 256, 256>>>(b1);
    gemm2_kernel<<<(NN + 255) / 256, 256>>>(W2, r2w);
    edge_agg2<<<(NN * 32 + 255) / 256, 256>>>(b2, out);
}